// round 5
// baseline (speedup 1.0000x reference)
#include <cuda_runtime.h>
#include <cuda_bf16.h>

#define B_SZ 32
#define F_SZ 257
#define T_SZ 3000
#define TCH 1500                 // t per chunk
#define TCH4 375                 // float4 per chunk-row
#define ROW4 750                 // float4 per full row
#define NFCH 16                  // F-chunks
#define FCHUNK 17                // 15*17=255, last chunk = 2 rows
#define THREADS 256
#define MOMENTUM 0.99f
#define ONE_MINUS_M 0.01f
#define EPS 1e-8f

#define NB_CS (2 * NFCH * B_SZ)         // 1024 colsum blocks (2 x-tiles of 256 over 375)
#define NB_NM (2 * F_SZ * B_SZ)         // 16448 normalize blocks

// Scratch (static device globals)
__device__ __align__(16) float g_part[NFCH * B_SZ * TCH];  // per-chunk partial colsums
__device__ __align__(16) float g_inv[B_SZ * TCH];          // per-chunk 1/(m+bias+eps)
__device__ float g_carry[B_SZ];                            // EMA state across chunks

// ---------------------------------------------------------------------------
// A-kernel: blocks [0, nb_cs) do column sums for chunk at tbase_cs;
//           blocks [nb_cs, nb_cs+nb_nm) normalize chunk at tbase_nm.
// ---------------------------------------------------------------------------
__global__ __launch_bounds__(THREADS)
void ema_A(const float* __restrict__ mag,
           float* __restrict__ out_norm,
           int nb_cs, int tbase_cs,
           int nb_nm, int tbase_nm) {
    const int bid = blockIdx.x;
    const int tid = threadIdx.x;

    if (bid < nb_cs) {
        // ---------------- column-sum part ----------------
        int cid = bid;
        int xi  = cid & 1;
        int ch  = (cid >> 1) & (NFCH - 1);
        int b   = cid >> 5;                 // cid / 32
        int t4  = xi * THREADS + tid;
        if (t4 >= TCH4) return;

        int f0 = ch * FCHUNK;
        int f1 = f0 + FCHUNK;
        if (f1 > F_SZ) f1 = F_SZ;

        const float4* base = reinterpret_cast<const float4*>(mag)
                           + (size_t)b * F_SZ * ROW4 + (tbase_cs >> 2) + t4;

        float4 s = make_float4(0.f, 0.f, 0.f, 0.f);
        int f = f0;
        #pragma unroll 1
        for (; f + 8 <= f1; f += 8) {
            float4 v0 = base[(size_t)(f + 0) * ROW4];
            float4 v1 = base[(size_t)(f + 1) * ROW4];
            float4 v2 = base[(size_t)(f + 2) * ROW4];
            float4 v3 = base[(size_t)(f + 3) * ROW4];
            float4 v4 = base[(size_t)(f + 4) * ROW4];
            float4 v5 = base[(size_t)(f + 5) * ROW4];
            float4 v6 = base[(size_t)(f + 6) * ROW4];
            float4 v7 = base[(size_t)(f + 7) * ROW4];
            s.x += ((v0.x + v1.x) + (v2.x + v3.x)) + ((v4.x + v5.x) + (v6.x + v7.x));
            s.y += ((v0.y + v1.y) + (v2.y + v3.y)) + ((v4.y + v5.y) + (v6.y + v7.y));
            s.z += ((v0.z + v1.z) + (v2.z + v3.z)) + ((v4.z + v5.z) + (v6.z + v7.z));
            s.w += ((v0.w + v1.w) + (v2.w + v3.w)) + ((v4.w + v5.w) + (v6.w + v7.w));
        }
        for (; f < f1; f++) {
            float4 v = base[(size_t)f * ROW4];
            s.x += v.x; s.y += v.y; s.z += v.z; s.w += v.w;
        }
        reinterpret_cast<float4*>(g_part)[((size_t)ch * B_SZ + b) * TCH4 + t4] = s;
    } else if (bid < nb_cs + nb_nm) {
        // ---------------- normalize part ----------------
        int nid = bid - nb_cs;
        int xi  = nid & 1;
        int f   = (nid >> 1) % F_SZ;
        int b   = (nid >> 1) / F_SZ;
        int t4  = xi * THREADS + tid;
        if (t4 >= TCH4) return;

        size_t idx = ((size_t)b * F_SZ + f) * ROW4 + (tbase_nm >> 2) + t4;
        float4 v  = reinterpret_cast<const float4*>(mag)[idx];
        float4 iv = reinterpret_cast<const float4*>(g_inv)[(size_t)b * TCH4 + t4];
        v.x *= iv.x; v.y *= iv.y; v.z *= iv.z; v.w *= iv.w;
        __stcs(reinterpret_cast<float4*>(out_norm) + idx, v);
    }
}

// ---------------------------------------------------------------------------
// k2: per-batch EMA scan of one 1500-step chunk.
// Coalesced smem staging for the 16-way partial reduce; block pair-scan;
// coalesced flush of inv + mean. grid: 32 blocks x 256.
// ---------------------------------------------------------------------------
#define SEG 6                     // 256 * 6 = 1536 >= 1500
__global__ __launch_bounds__(THREADS)
void ema_k2_scan(const float* __restrict__ bias,
                 const float* __restrict__ running_mean,
                 float* __restrict__ out_mean,
                 int chunk, int tbase) {
    __shared__ float s_buf[2 * TCH];          // staging: x, then inv|mean
    __shared__ float sA[THREADS], sB[THREADS];
    const int b   = blockIdx.x;
    const int tid = threadIdx.x;

    // coalesced 16-way reduction into s_buf[0..1500)
    for (int t = tid; t < TCH; t += THREADS) {
        float acc = 0.f;
        #pragma unroll
        for (int c = 0; c < NFCH; c++)
            acc += g_part[((size_t)c * B_SZ + b) * TCH + t];
        s_buf[t] = acc * (1.0f / (float)F_SZ);
    }
    __syncthreads();

    // per-thread serial composition over its segment
    float x[SEG];
    float A = 1.0f, Bc = 0.0f;
    const int t0 = tid * SEG;
    #pragma unroll
    for (int j = 0; j < SEG; j++) {
        int t = t0 + j;
        if (t < TCH) {
            float fm = s_buf[t];
            x[j] = fm;
            A  *= MOMENTUM;
            Bc  = MOMENTUM * Bc + ONE_MINUS_M * fm;
        }
    }
    __syncthreads();

    // block inclusive pair-scan: (a2,b2)∘(a1,b1) = (a2*a1, a2*b1+b2)
    sA[tid] = A; sB[tid] = Bc;
    __syncthreads();
    #pragma unroll
    for (int off = 1; off < THREADS; off <<= 1) {
        float a2 = sA[tid], b2 = sB[tid];
        float a1 = 1.0f, b1 = 0.0f;
        if (tid >= off) { a1 = sA[tid - off]; b1 = sB[tid - off]; }
        __syncthreads();
        sA[tid] = a2 * a1;
        sB[tid] = a2 * b1 + b2;
        __syncthreads();
    }

    float Ap = 1.0f, Bp = 0.0f;
    if (tid > 0) { Ap = sA[tid - 1]; Bp = sB[tid - 1]; }

    float init = (chunk == 0) ? running_mean[0] : g_carry[b];
    float m    = Ap * init + Bp;
    const float bi = bias[0];

    #pragma unroll
    for (int j = 0; j < SEG; j++) {
        int t = t0 + j;
        if (t < TCH) {
            m = MOMENTUM * m + ONE_MINUS_M * x[j];
            float mwb = m + bi;
            s_buf[t]       = 1.0f / (mwb + EPS);   // inv
            s_buf[TCH + t] = mwb;                  // mean
            if (t == TCH - 1) g_carry[b] = m;
        }
    }
    __syncthreads();

    // coalesced flush
    float* invp  = g_inv + (size_t)b * TCH;
    float* meanp = out_mean + (size_t)b * T_SZ + tbase;
    for (int t = tid; t < TCH; t += THREADS) {
        invp[t]  = s_buf[t];
        meanp[t] = s_buf[TCH + t];
    }
}

// ---------------------------------------------------------------------------
extern "C" void kernel_launch(void* const* d_in, const int* in_sizes, int n_in,
                              void* d_out, int out_size) {
    const float* mag          = (const float*)d_in[0];
    const float* bias         = (const float*)d_in[1];
    const float* running_mean = (const float*)d_in[2];
    float* out = (float*)d_out;

    float* out_norm = out;                                // [B, F, T]
    float* out_mean = out + (size_t)B_SZ * F_SZ * T_SZ;   // [B, 1, T]

    // A0: colsum chunk 0
    ema_A<<<NB_CS, THREADS>>>(mag, out_norm, NB_CS, 0, 0, 0);
    // scan chunk 0
    ema_k2_scan<<<B_SZ, THREADS>>>(bias, running_mean, out_mean, 0, 0);
    // A1: colsum chunk 1 + normalize chunk 0
    ema_A<<<NB_CS + NB_NM, THREADS>>>(mag, out_norm, NB_CS, TCH, NB_NM, 0);
    // scan chunk 1
    ema_k2_scan<<<B_SZ, THREADS>>>(bias, running_mean, out_mean, 1, TCH);
    // A2: normalize chunk 1
    ema_A<<<NB_NM, THREADS>>>(mag, out_norm, 0, 0, NB_NM, TCH);
}

// round 6
// speedup vs baseline: 1.2784x; 1.2784x over previous
#include <cuda_runtime.h>
#include <cuda_bf16.h>

#define B_SZ 32
#define F_SZ 257
#define T_SZ 3000
#define T4_SZ 750                 // float4 per row
#define NCHUNK 16
#define FCHUNK 17                 // 15*17 = 255, last chunk = 2 rows
#define MOMENTUM 0.99f
#define ONE_MINUS_M 0.01f
#define EPS 1e-8f

// Scratch (static device globals)
__device__ __align__(16) float g_part[NCHUNK * B_SZ * T_SZ];  // partial colsums
__device__ __align__(16) float g_fm[B_SZ * T_SZ];             // frame means
__device__ __align__(16) float g_inv[B_SZ * T_SZ];            // 1/(mean+bias+eps)

// ---------------------------------------------------------------------------
// k1: partial column sums over F-chunks, float4 vectorized over T.
// grid: (6, NCHUNK, B), block 128.  8-deep load batching for MLP.
// ---------------------------------------------------------------------------
__global__ __launch_bounds__(128)
void ema_k1_colsum(const float* __restrict__ mag) {
    int t4 = blockIdx.x * blockDim.x + threadIdx.x;
    if (t4 >= T4_SZ) return;
    int ch = blockIdx.y;
    int b  = blockIdx.z;

    int f0 = ch * FCHUNK;
    int f1 = f0 + FCHUNK;
    if (f1 > F_SZ) f1 = F_SZ;

    const float4* base = reinterpret_cast<const float4*>(mag)
                       + (size_t)b * F_SZ * T4_SZ + t4;

    float4 s = make_float4(0.f, 0.f, 0.f, 0.f);
    int f = f0;
    #pragma unroll 1
    for (; f + 8 <= f1; f += 8) {
        float4 v0 = base[(size_t)(f + 0) * T4_SZ];
        float4 v1 = base[(size_t)(f + 1) * T4_SZ];
        float4 v2 = base[(size_t)(f + 2) * T4_SZ];
        float4 v3 = base[(size_t)(f + 3) * T4_SZ];
        float4 v4 = base[(size_t)(f + 4) * T4_SZ];
        float4 v5 = base[(size_t)(f + 5) * T4_SZ];
        float4 v6 = base[(size_t)(f + 6) * T4_SZ];
        float4 v7 = base[(size_t)(f + 7) * T4_SZ];
        s.x += ((v0.x + v1.x) + (v2.x + v3.x)) + ((v4.x + v5.x) + (v6.x + v7.x));
        s.y += ((v0.y + v1.y) + (v2.y + v3.y)) + ((v4.y + v5.y) + (v6.y + v7.y));
        s.z += ((v0.z + v1.z) + (v2.z + v3.z)) + ((v4.z + v5.z) + (v6.z + v7.z));
        s.w += ((v0.w + v1.w) + (v2.w + v3.w)) + ((v4.w + v5.w) + (v6.w + v7.w));
    }
    for (; f < f1; f++) {
        float4 v = base[(size_t)f * T4_SZ];
        s.x += v.x; s.y += v.y; s.z += v.z; s.w += v.w;
    }
    reinterpret_cast<float4*>(g_part)[((size_t)ch * B_SZ + b) * T4_SZ + t4] = s;
}

// ---------------------------------------------------------------------------
// k1b: collapse NCHUNK partials -> frame means.  Wide grid, full bandwidth.
// Elements: B*T/4 = 24000 float4.  grid 94 x 256.
// ---------------------------------------------------------------------------
__global__ __launch_bounds__(256)
void ema_k1b_reduce() {
    int i = blockIdx.x * blockDim.x + threadIdx.x;     // float4 index in [B*T/4)
    if (i >= (B_SZ * T_SZ) / 4) return;
    const float4* p = reinterpret_cast<const float4*>(g_part);
    float4 s = make_float4(0.f, 0.f, 0.f, 0.f);
    #pragma unroll
    for (int c = 0; c < NCHUNK; c++) {
        float4 v = p[(size_t)c * (B_SZ * T_SZ / 4) + i];
        s.x += v.x; s.y += v.y; s.z += v.z; s.w += v.w;
    }
    const float inv_f = 1.0f / (float)F_SZ;
    s.x *= inv_f; s.y *= inv_f; s.z *= inv_f; s.w *= inv_f;
    reinterpret_cast<float4*>(g_fm)[i] = s;
}

// ---------------------------------------------------------------------------
// k2: per-batch EMA scan over T=3000.  grid: B x 256, SEG=12.
// Reads only 12KB/block of frame means; smem-staged coalesced I/O.
// ---------------------------------------------------------------------------
#define SCAN_THREADS 256
#define SEG 12
__global__ __launch_bounds__(SCAN_THREADS)
void ema_k2_scan(const float* __restrict__ bias,
                 const float* __restrict__ running_mean,
                 float* __restrict__ out_mean) {
    __shared__ float s_buf[2 * T_SZ > 6144 ? 2 * T_SZ : 6144]; // 24KB
    __shared__ float sA[SCAN_THREADS], sB[SCAN_THREADS];
    const int b   = blockIdx.x;
    const int tid = threadIdx.x;

    // coalesced load of frame means
    for (int t = tid; t < T_SZ; t += SCAN_THREADS)
        s_buf[t] = g_fm[(size_t)b * T_SZ + t];
    __syncthreads();

    // per-thread serial composition over its segment
    float x[SEG];
    float A = 1.0f, Bc = 0.0f;
    const int t0 = tid * SEG;
    #pragma unroll
    for (int j = 0; j < SEG; j++) {
        int t = t0 + j;
        if (t < T_SZ) {
            float fm = s_buf[t];
            x[j] = fm;
            A  *= MOMENTUM;
            Bc  = MOMENTUM * Bc + ONE_MINUS_M * fm;
        }
    }
    __syncthreads();

    // block inclusive pair-scan: (a2,b2)∘(a1,b1) = (a2*a1, a2*b1+b2)
    sA[tid] = A; sB[tid] = Bc;
    __syncthreads();
    #pragma unroll
    for (int off = 1; off < SCAN_THREADS; off <<= 1) {
        float a2 = sA[tid], b2 = sB[tid];
        float a1 = 1.0f, b1 = 0.0f;
        if (tid >= off) { a1 = sA[tid - off]; b1 = sB[tid - off]; }
        __syncthreads();
        sA[tid] = a2 * a1;
        sB[tid] = a2 * b1 + b2;
        __syncthreads();
    }

    float Ap = 1.0f, Bp = 0.0f;
    if (tid > 0) { Ap = sA[tid - 1]; Bp = sB[tid - 1]; }

    float m = Ap * running_mean[0] + Bp;
    const float bi = bias[0];

    #pragma unroll
    for (int j = 0; j < SEG; j++) {
        int t = t0 + j;
        if (t < T_SZ) {
            m = MOMENTUM * m + ONE_MINUS_M * x[j];
            float mwb = m + bi;
            s_buf[t]        = 1.0f / (mwb + EPS);   // inv
            s_buf[T_SZ + t] = mwb;                  // mean
        }
    }
    __syncthreads();

    // coalesced flush
    float* invp  = g_inv + (size_t)b * T_SZ;
    float* meanp = out_mean + (size_t)b * T_SZ;
    for (int t = tid; t < T_SZ; t += SCAN_THREADS) {
        invp[t]  = s_buf[t];
        meanp[t] = s_buf[T_SZ + t];
    }
}

// ---------------------------------------------------------------------------
// k3: mag_norm = mag * inv[b,t], float4, streaming stores.
// grid: (3, F, B), block 256.
// ---------------------------------------------------------------------------
__global__ __launch_bounds__(256)
void ema_k3_norm(const float* __restrict__ mag,
                 float* __restrict__ out_norm) {
    int t4 = blockIdx.x * blockDim.x + threadIdx.x;
    if (t4 >= T4_SZ) return;
    int f = blockIdx.y;
    int b = blockIdx.z;

    size_t idx = ((size_t)b * F_SZ + f) * T4_SZ + t4;
    float4 v  = reinterpret_cast<const float4*>(mag)[idx];
    float4 iv = __ldca(reinterpret_cast<const float4*>(g_inv) + (size_t)b * T4_SZ + t4);
    v.x *= iv.x; v.y *= iv.y; v.z *= iv.z; v.w *= iv.w;
    __stcs(reinterpret_cast<float4*>(out_norm) + idx, v);
}

// ---------------------------------------------------------------------------
extern "C" void kernel_launch(void* const* d_in, const int* in_sizes, int n_in,
                              void* d_out, int out_size) {
    const float* mag          = (const float*)d_in[0];
    const float* bias         = (const float*)d_in[1];
    const float* running_mean = (const float*)d_in[2];
    float* out = (float*)d_out;

    float* out_norm = out;                                // [B, F, T]
    float* out_mean = out + (size_t)B_SZ * F_SZ * T_SZ;   // [B, 1, T]

    {   // k1: partial column sums (3072 blocks)
        dim3 grid((T4_SZ + 127) / 128, NCHUNK, B_SZ);
        ema_k1_colsum<<<grid, 128>>>(mag);
    }
    {   // k1b: partials -> frame means (wide)
        int n4 = (B_SZ * T_SZ) / 4;
        ema_k1b_reduce<<<(n4 + 255) / 256, 256>>>();
    }
    // k2: scan (tiny reads now)
    ema_k2_scan<<<B_SZ, SCAN_THREADS>>>(bias, running_mean, out_mean);
    {   // k3: normalize
        dim3 grid((T4_SZ + 255) / 256, F_SZ, B_SZ);
        ema_k3_norm<<<grid, 256>>>(mag, out_norm);
    }
}

// round 7
// speedup vs baseline: 1.4952x; 1.1696x over previous
#include <cuda_runtime.h>
#include <cuda_bf16.h>

#define B_SZ 32
#define F_SZ 257
#define T_SZ 3000
#define T4_SZ 750                 // float4 per row
#define NCHUNK 8
#define FCHUNK 33                 // 7*33 = 231, last chunk = 26 rows
#define MOMENTUM 0.99f
#define ONE_MINUS_M 0.01f
#define EPS 1e-8f

// Scratch (static device globals)
__device__ __align__(16) float g_part[NCHUNK * B_SZ * T_SZ];  // partial colsums
__device__ __align__(16) float g_fm[B_SZ * T_SZ];             // frame means
__device__ __align__(16) float g_inv[B_SZ * T_SZ];            // 1/(mean+bias+eps)

// ---------------------------------------------------------------------------
// k1: partial column sums over F-chunks, float4 vectorized over T.
// grid: (6, NCHUNK, B) = 1536 blocks, block 128.  8-deep load batching (MLP).
// ---------------------------------------------------------------------------
__global__ __launch_bounds__(128)
void ema_k1_colsum(const float* __restrict__ mag) {
    int t4 = blockIdx.x * blockDim.x + threadIdx.x;
    if (t4 >= T4_SZ) return;
    int ch = blockIdx.y;
    int b  = blockIdx.z;

    int f0 = ch * FCHUNK;
    int f1 = f0 + FCHUNK;
    if (f1 > F_SZ) f1 = F_SZ;

    const float4* base = reinterpret_cast<const float4*>(mag)
                       + (size_t)b * F_SZ * T4_SZ + t4;

    float4 s = make_float4(0.f, 0.f, 0.f, 0.f);
    int f = f0;
    #pragma unroll 1
    for (; f + 8 <= f1; f += 8) {
        float4 v0 = base[(size_t)(f + 0) * T4_SZ];
        float4 v1 = base[(size_t)(f + 1) * T4_SZ];
        float4 v2 = base[(size_t)(f + 2) * T4_SZ];
        float4 v3 = base[(size_t)(f + 3) * T4_SZ];
        float4 v4 = base[(size_t)(f + 4) * T4_SZ];
        float4 v5 = base[(size_t)(f + 5) * T4_SZ];
        float4 v6 = base[(size_t)(f + 6) * T4_SZ];
        float4 v7 = base[(size_t)(f + 7) * T4_SZ];
        s.x += ((v0.x + v1.x) + (v2.x + v3.x)) + ((v4.x + v5.x) + (v6.x + v7.x));
        s.y += ((v0.y + v1.y) + (v2.y + v3.y)) + ((v4.y + v5.y) + (v6.y + v7.y));
        s.z += ((v0.z + v1.z) + (v2.z + v3.z)) + ((v4.z + v5.z) + (v6.z + v7.z));
        s.w += ((v0.w + v1.w) + (v2.w + v3.w)) + ((v4.w + v5.w) + (v6.w + v7.w));
    }
    for (; f < f1; f++) {
        float4 v = base[(size_t)f * T4_SZ];
        s.x += v.x; s.y += v.y; s.z += v.z; s.w += v.w;
    }
    reinterpret_cast<float4*>(g_part)[((size_t)ch * B_SZ + b) * T4_SZ + t4] = s;
}

// ---------------------------------------------------------------------------
// k1b: collapse NCHUNK partials -> frame means.  grid 94 x 256.
// ---------------------------------------------------------------------------
__global__ __launch_bounds__(256)
void ema_k1b_reduce() {
    int i = blockIdx.x * blockDim.x + threadIdx.x;     // float4 index in [B*T/4)
    if (i >= (B_SZ * T_SZ) / 4) return;
    const float4* p = reinterpret_cast<const float4*>(g_part);
    float4 s = make_float4(0.f, 0.f, 0.f, 0.f);
    #pragma unroll
    for (int c = 0; c < NCHUNK; c++) {
        float4 v = p[(size_t)c * (B_SZ * T_SZ / 4) + i];
        s.x += v.x; s.y += v.y; s.z += v.z; s.w += v.w;
    }
    const float inv_f = 1.0f / (float)F_SZ;
    s.x *= inv_f; s.y *= inv_f; s.z *= inv_f; s.w *= inv_f;
    reinterpret_cast<float4*>(g_fm)[i] = s;
}

// ---------------------------------------------------------------------------
// k2: per-batch EMA scan over T=3000.  grid: B x 256, SEG=12.
// Reads only 12 KB/block of frame means; smem-staged coalesced I/O.
// ---------------------------------------------------------------------------
#define SCAN_THREADS 256
#define SEG 12
__global__ __launch_bounds__(SCAN_THREADS)
void ema_k2_scan(const float* __restrict__ bias,
                 const float* __restrict__ running_mean,
                 float* __restrict__ out_mean) {
    __shared__ float s_buf[2 * T_SZ];
    __shared__ float sA[SCAN_THREADS], sB[SCAN_THREADS];
    const int b   = blockIdx.x;
    const int tid = threadIdx.x;

    for (int t = tid; t < T_SZ; t += SCAN_THREADS)
        s_buf[t] = g_fm[(size_t)b * T_SZ + t];
    __syncthreads();

    float x[SEG];
    float A = 1.0f, Bc = 0.0f;
    const int t0 = tid * SEG;
    #pragma unroll
    for (int j = 0; j < SEG; j++) {
        int t = t0 + j;
        if (t < T_SZ) {
            float fm = s_buf[t];
            x[j] = fm;
            A  *= MOMENTUM;
            Bc  = MOMENTUM * Bc + ONE_MINUS_M * fm;
        }
    }
    __syncthreads();

    sA[tid] = A; sB[tid] = Bc;
    __syncthreads();
    #pragma unroll
    for (int off = 1; off < SCAN_THREADS; off <<= 1) {
        float a2 = sA[tid], b2 = sB[tid];
        float a1 = 1.0f, b1 = 0.0f;
        if (tid >= off) { a1 = sA[tid - off]; b1 = sB[tid - off]; }
        __syncthreads();
        sA[tid] = a2 * a1;
        sB[tid] = a2 * b1 + b2;
        __syncthreads();
    }

    float Ap = 1.0f, Bp = 0.0f;
    if (tid > 0) { Ap = sA[tid - 1]; Bp = sB[tid - 1]; }

    float m = Ap * running_mean[0] + Bp;
    const float bi = bias[0];

    #pragma unroll
    for (int j = 0; j < SEG; j++) {
        int t = t0 + j;
        if (t < T_SZ) {
            m = MOMENTUM * m + ONE_MINUS_M * x[j];
            float mwb = m + bi;
            s_buf[t]        = 1.0f / (mwb + EPS);   // inv
            s_buf[T_SZ + t] = mwb;                  // mean
        }
    }
    __syncthreads();

    float* invp  = g_inv + (size_t)b * T_SZ;
    float* meanp = out_mean + (size_t)b * T_SZ;
    for (int t = tid; t < T_SZ; t += SCAN_THREADS) {
        invp[t]  = s_buf[t];
        meanp[t] = s_buf[T_SZ + t];
    }
}

// ---------------------------------------------------------------------------
// k3: mag_norm = mag * inv[b,t]; each thread handles 2 f-rows per iv load
// (halves inv read traffic).  grid: (3, 129, 32), block 256.
// ---------------------------------------------------------------------------
__global__ __launch_bounds__(256)
void ema_k3_norm(const float* __restrict__ mag,
                 float* __restrict__ out_norm) {
    int t4 = blockIdx.x * blockDim.x + threadIdx.x;
    if (t4 >= T4_SZ) return;
    int f = blockIdx.y * 2;          // 0, 2, ..., 256
    int b = blockIdx.z;

    float4 iv = __ldca(reinterpret_cast<const float4*>(g_inv) + (size_t)b * T4_SZ + t4);

    size_t idx0 = ((size_t)b * F_SZ + f) * T4_SZ + t4;
    float4 v0 = reinterpret_cast<const float4*>(mag)[idx0];
    bool has2 = (f + 1) < F_SZ;
    float4 v1;
    if (has2) v1 = reinterpret_cast<const float4*>(mag)[idx0 + T4_SZ];

    v0.x *= iv.x; v0.y *= iv.y; v0.z *= iv.z; v0.w *= iv.w;
    __stcs(reinterpret_cast<float4*>(out_norm) + idx0, v0);
    if (has2) {
        v1.x *= iv.x; v1.y *= iv.y; v1.z *= iv.z; v1.w *= iv.w;
        __stcs(reinterpret_cast<float4*>(out_norm) + idx0 + T4_SZ, v1);
    }
}

// ---------------------------------------------------------------------------
extern "C" void kernel_launch(void* const* d_in, const int* in_sizes, int n_in,
                              void* d_out, int out_size) {
    const float* mag          = (const float*)d_in[0];
    const float* bias         = (const float*)d_in[1];
    const float* running_mean = (const float*)d_in[2];
    float* out = (float*)d_out;

    float* out_norm = out;                                // [B, F, T]
    float* out_mean = out + (size_t)B_SZ * F_SZ * T_SZ;   // [B, 1, T]

    {   // k1: partial column sums (1536 blocks)
        dim3 grid((T4_SZ + 127) / 128, NCHUNK, B_SZ);
        ema_k1_colsum<<<grid, 128>>>(mag);
    }
    {   // k1b: partials -> frame means
        int n4 = (B_SZ * T_SZ) / 4;
        ema_k1b_reduce<<<(n4 + 255) / 256, 256>>>();
    }
    // k2: scan
    ema_k2_scan<<<B_SZ, SCAN_THREADS>>>(bias, running_mean, out_mean);
    {   // k3: normalize (2 rows / thread)
        dim3 grid((T4_SZ + 255) / 256, (F_SZ + 1) / 2, B_SZ);
        ema_k3_norm<<<grid, 256>>>(mag, out_norm);
    }
}

// round 8
// speedup vs baseline: 1.5060x; 1.0072x over previous
#include <cuda_runtime.h>
#include <cuda_bf16.h>

#define B_SZ 32
#define F_SZ 257
#define T_SZ 3000
#define T4_SZ 750                 // float4 per row
#define NCHUNK 8
#define FCHUNK 33                 // 7*33 = 231, last chunk = 26 rows
#define NXT 6                     // t4 tiles of 128
#define MOMENTUM 0.99f
#define ONE_MINUS_M 0.01f
#define EPS 1e-8f

// Scratch (static device globals)
__device__ __align__(16) float g_part[NCHUNK * B_SZ * T_SZ];  // partial colsums
__device__ __align__(16) float g_fm[B_SZ * T_SZ];             // frame means
__device__ __align__(16) float g_inv[B_SZ * T_SZ];            // 1/(mean+bias+eps)
__device__ int g_cnt[NXT * B_SZ];                             // arrival counters (self-reset)

// ---------------------------------------------------------------------------
// k1: partial column sums over F-chunks + folded final reduce.
// grid: (NXT, NCHUNK, B) = 1536 blocks, block 128.
// Last-arriving chunk block per (xtile, b) reduces partials -> g_fm.
// ---------------------------------------------------------------------------
__global__ __launch_bounds__(128)
void ema_k1_colsum(const float* __restrict__ mag) {
    const int tid = threadIdx.x;
    const int t4  = blockIdx.x * 128 + tid;
    const int ch  = blockIdx.y;
    const int b   = blockIdx.z;

    if (t4 < T4_SZ) {
        int f0 = ch * FCHUNK;
        int f1 = f0 + FCHUNK;
        if (f1 > F_SZ) f1 = F_SZ;

        const float4* base = reinterpret_cast<const float4*>(mag)
                           + (size_t)b * F_SZ * T4_SZ + t4;

        float4 s = make_float4(0.f, 0.f, 0.f, 0.f);
        int f = f0;
        #pragma unroll 1
        for (; f + 8 <= f1; f += 8) {
            float4 v0 = base[(size_t)(f + 0) * T4_SZ];
            float4 v1 = base[(size_t)(f + 1) * T4_SZ];
            float4 v2 = base[(size_t)(f + 2) * T4_SZ];
            float4 v3 = base[(size_t)(f + 3) * T4_SZ];
            float4 v4 = base[(size_t)(f + 4) * T4_SZ];
            float4 v5 = base[(size_t)(f + 5) * T4_SZ];
            float4 v6 = base[(size_t)(f + 6) * T4_SZ];
            float4 v7 = base[(size_t)(f + 7) * T4_SZ];
            s.x += ((v0.x + v1.x) + (v2.x + v3.x)) + ((v4.x + v5.x) + (v6.x + v7.x));
            s.y += ((v0.y + v1.y) + (v2.y + v3.y)) + ((v4.y + v5.y) + (v6.y + v7.y));
            s.z += ((v0.z + v1.z) + (v2.z + v3.z)) + ((v4.z + v5.z) + (v6.z + v7.z));
            s.w += ((v0.w + v1.w) + (v2.w + v3.w)) + ((v4.w + v5.w) + (v6.w + v7.w));
        }
        for (; f < f1; f++) {
            float4 v = base[(size_t)f * T4_SZ];
            s.x += v.x; s.y += v.y; s.z += v.z; s.w += v.w;
        }
        reinterpret_cast<float4*>(g_part)[((size_t)ch * B_SZ + b) * T4_SZ + t4] = s;
    }

    // ---- last-arriver folds the NCHUNK partials into g_fm -----------------
    __threadfence();                 // release our partial writes
    __syncthreads();
    __shared__ int s_last;
    if (tid == 0)
        s_last = (atomicAdd(&g_cnt[blockIdx.x * B_SZ + b], 1) == NCHUNK - 1);
    __syncthreads();
    if (!s_last) return;

    if (t4 < T4_SZ) {
        const float4* p = reinterpret_cast<const float4*>(g_part);
        float4 s = make_float4(0.f, 0.f, 0.f, 0.f);
        #pragma unroll
        for (int c = 0; c < NCHUNK; c++) {
            float4 v = __ldcg(p + (size_t)c * (B_SZ * T4_SZ) + (size_t)b * T4_SZ + t4);
            s.x += v.x; s.y += v.y; s.z += v.z; s.w += v.w;
        }
        const float inv_f = 1.0f / (float)F_SZ;
        s.x *= inv_f; s.y *= inv_f; s.z *= inv_f; s.w *= inv_f;
        reinterpret_cast<float4*>(g_fm)[(size_t)b * T4_SZ + t4] = s;
    }
    __syncthreads();
    if (tid == 0) atomicExch(&g_cnt[blockIdx.x * B_SZ + b], 0);  // replay-safe reset
}

// ---------------------------------------------------------------------------
// k2: per-batch EMA scan over T=3000.  grid: B x 256, SEG=12.
// ---------------------------------------------------------------------------
#define SCAN_THREADS 256
#define SEG 12
__global__ __launch_bounds__(SCAN_THREADS)
void ema_k2_scan(const float* __restrict__ bias,
                 const float* __restrict__ running_mean,
                 float* __restrict__ out_mean) {
    __shared__ float s_buf[2 * T_SZ];
    __shared__ float sA[SCAN_THREADS], sB[SCAN_THREADS];
    const int b   = blockIdx.x;
    const int tid = threadIdx.x;

    for (int t = tid; t < T_SZ; t += SCAN_THREADS)
        s_buf[t] = g_fm[(size_t)b * T_SZ + t];
    __syncthreads();

    float x[SEG];
    float A = 1.0f, Bc = 0.0f;
    const int t0 = tid * SEG;
    #pragma unroll
    for (int j = 0; j < SEG; j++) {
        int t = t0 + j;
        if (t < T_SZ) {
            float fm = s_buf[t];
            x[j] = fm;
            A  *= MOMENTUM;
            Bc  = MOMENTUM * Bc + ONE_MINUS_M * fm;
        }
    }
    __syncthreads();

    sA[tid] = A; sB[tid] = Bc;
    __syncthreads();
    #pragma unroll
    for (int off = 1; off < SCAN_THREADS; off <<= 1) {
        float a2 = sA[tid], b2 = sB[tid];
        float a1 = 1.0f, b1 = 0.0f;
        if (tid >= off) { a1 = sA[tid - off]; b1 = sB[tid - off]; }
        __syncthreads();
        sA[tid] = a2 * a1;
        sB[tid] = a2 * b1 + b2;
        __syncthreads();
    }

    float Ap = 1.0f, Bp = 0.0f;
    if (tid > 0) { Ap = sA[tid - 1]; Bp = sB[tid - 1]; }

    float m = Ap * running_mean[0] + Bp;
    const float bi = bias[0];

    #pragma unroll
    for (int j = 0; j < SEG; j++) {
        int t = t0 + j;
        if (t < T_SZ) {
            m = MOMENTUM * m + ONE_MINUS_M * x[j];
            float mwb = m + bi;
            s_buf[t]        = 1.0f / (mwb + EPS);   // inv
            s_buf[T_SZ + t] = mwb;                  // mean
        }
    }
    __syncthreads();

    float* invp  = g_inv + (size_t)b * T_SZ;
    float* meanp = out_mean + (size_t)b * T_SZ;
    for (int t = tid; t < T_SZ; t += SCAN_THREADS) {
        invp[t]  = s_buf[t];
        meanp[t] = s_buf[T_SZ + t];
    }
}

// ---------------------------------------------------------------------------
// k3: mag_norm = mag * inv[b,t]; 4 f-rows per iv load; reverse-b so earliest
// blocks hit the freshest L2-resident mag from k1's tail.
// grid: (3, 65, 32), block 256.
// ---------------------------------------------------------------------------
__global__ __launch_bounds__(256)
void ema_k3_norm(const float* __restrict__ mag,
                 float* __restrict__ out_norm) {
    int t4 = blockIdx.x * blockDim.x + threadIdx.x;
    if (t4 >= T4_SZ) return;
    int f0 = blockIdx.y * 4;                 // 0,4,...,256
    int b  = (B_SZ - 1) - blockIdx.z;

    float4 iv = __ldca(reinterpret_cast<const float4*>(g_inv) + (size_t)b * T4_SZ + t4);

    const int nrows = (F_SZ - f0) < 4 ? (F_SZ - f0) : 4;
    size_t idx0 = ((size_t)b * F_SZ + f0) * T4_SZ + t4;

    float4 v[4];
    #pragma unroll
    for (int r = 0; r < 4; r++)
        if (r < nrows) v[r] = reinterpret_cast<const float4*>(mag)[idx0 + (size_t)r * T4_SZ];

    #pragma unroll
    for (int r = 0; r < 4; r++) {
        if (r < nrows) {
            v[r].x *= iv.x; v[r].y *= iv.y; v[r].z *= iv.z; v[r].w *= iv.w;
            __stcs(reinterpret_cast<float4*>(out_norm) + idx0 + (size_t)r * T4_SZ, v[r]);
        }
    }
}

// ---------------------------------------------------------------------------
extern "C" void kernel_launch(void* const* d_in, const int* in_sizes, int n_in,
                              void* d_out, int out_size) {
    const float* mag          = (const float*)d_in[0];
    const float* bias         = (const float*)d_in[1];
    const float* running_mean = (const float*)d_in[2];
    float* out = (float*)d_out;

    float* out_norm = out;                                // [B, F, T]
    float* out_mean = out + (size_t)B_SZ * F_SZ * T_SZ;   // [B, 1, T]

    {   // k1: partial column sums + folded reduce
        dim3 grid(NXT, NCHUNK, B_SZ);
        ema_k1_colsum<<<grid, 128>>>(mag);
    }
    // k2: scan
    ema_k2_scan<<<B_SZ, SCAN_THREADS>>>(bias, running_mean, out_mean);
    {   // k3: normalize (4 rows / thread, reverse-b)
        dim3 grid(3, (F_SZ + 3) / 4, B_SZ);
        ema_k3_norm<<<grid, 256>>>(mag, out_norm);
    }
}